// round 1
// baseline (speedup 1.0000x reference)
#include <cuda_runtime.h>
#include <cuda_bf16.h>
#include <math.h>

// ---------------------------------------------------------------------------
// RelationalMemoryCell  (B=2048, S=8, H=8, HS=128, M=1024, QKV=384, IN=1024)
// fp32 baseline: tiled SGEMM + fused attention/gating kernels.
// ---------------------------------------------------------------------------

#define B_     2048
#define S_     8
#define H_     8
#define M_     1024
#define QKV_   384
#define TOT_   3072     // H_*QKV_
#define SP1_   9        // S_+1
#define ROWS_  (B_*SP1_)  // 18432

// Scratch (allocation-free rule: __device__ globals)
__device__ float g_x   [(size_t)B_   * M_  ];   // inputs @ kernel_in + bias
__device__ float g_mpi [(size_t)ROWS_* M_  ];   // concat(mem, x)
__device__ float g_qkv [(size_t)ROWS_* TOT_];   // mpi @ kernel_qkv + bias
__device__ float g_m1  [(size_t)ROWS_* M_  ];   // mpi + att
__device__ float g_h   [(size_t)ROWS_* M_  ];   // relu(m1 @ k0 + b0)
__device__ float g_m2  [(size_t)ROWS_* M_  ];   // m1 + h @ k1 + b1
__device__ float g_gi  [(size_t)B_ * 2];        // x @ kernel_gi + bias_gi

// ---------------------------------------------------------------------------
// SGEMM: C[M,N] = epilogue(A[M,K] @ B[K,N] + bias[N])
// MODE 0: plain+bias   MODE 1: relu(.+bias)   MODE 2: Cadd + (.+bias)
// 128x128 tile, BK=8, 256 threads, 8x8 per-thread microtile.
// All shapes here are multiples of (128,128,8) -> no bounds checks.
// ---------------------------------------------------------------------------
#define BM 128
#define BN 128
#define BK 8
#define TM 8
#define TN 8

template<int MODE>
__global__ __launch_bounds__(256)
void sgemm_kernel(const float* __restrict__ A, const float* __restrict__ Bm,
                  const float* __restrict__ bias, const float* __restrict__ Cadd,
                  float* __restrict__ C, int M, int N, int K)
{
    __shared__ float As[BK][BM];
    __shared__ float Bs[BK][BN];

    const int tid = threadIdx.x;
    const int bm  = blockIdx.y * BM;
    const int bn  = blockIdx.x * BN;

    const int ty = tid >> 4;        // 0..15  (rows:  ty*8 .. ty*8+7)
    const int tx = tid & 15;        // 0..15  (cols:  tx*8 .. tx*8+7)

    // A tile loaders: 128 rows x 8 cols = 256 float4
    const int arow = tid >> 1;          // 0..127
    const int acol = (tid & 1) * 4;     // 0 or 4
    // B tile loaders: 8 rows x 128 cols = 256 float4
    const int brow = tid >> 5;          // 0..7
    const int bcol = (tid & 31) << 2;   // 0..124

    const float* Aptr = A + (size_t)(bm + arow) * K + acol;
    const float* Bptr = Bm + (size_t)brow * N + bn + bcol;

    float acc[TM][TN];
    #pragma unroll
    for (int i = 0; i < TM; i++)
        #pragma unroll
        for (int j = 0; j < TN; j++) acc[i][j] = 0.f;

    for (int k0 = 0; k0 < K; k0 += BK) {
        float4 av = *(const float4*)Aptr;   Aptr += BK;
        float4 bv = *(const float4*)Bptr;   Bptr += (size_t)BK * N;

        As[acol + 0][arow] = av.x;
        As[acol + 1][arow] = av.y;
        As[acol + 2][arow] = av.z;
        As[acol + 3][arow] = av.w;
        *(float4*)&Bs[brow][bcol] = bv;
        __syncthreads();

        #pragma unroll
        for (int k = 0; k < BK; k++) {
            float4 a0 = *(const float4*)&As[k][ty * TM];
            float4 a1 = *(const float4*)&As[k][ty * TM + 4];
            float4 b0 = *(const float4*)&Bs[k][tx * TN];
            float4 b1 = *(const float4*)&Bs[k][tx * TN + 4];
            float a[TM] = {a0.x,a0.y,a0.z,a0.w,a1.x,a1.y,a1.z,a1.w};
            float b[TN] = {b0.x,b0.y,b0.z,b0.w,b1.x,b1.y,b1.z,b1.w};
            #pragma unroll
            for (int i = 0; i < TM; i++)
                #pragma unroll
                for (int j = 0; j < TN; j++)
                    acc[i][j] = fmaf(a[i], b[j], acc[i][j]);
        }
        __syncthreads();
    }

    // epilogue
    float bv[TN];
    #pragma unroll
    for (int j = 0; j < TN; j++) bv[j] = bias[bn + tx * TN + j];

    #pragma unroll
    for (int i = 0; i < TM; i++) {
        const size_t crow = (size_t)(bm + ty * TM + i);
        float* Crow = C + crow * N + bn + tx * TN;
        const float* Arow2 = (MODE == 2) ? (Cadd + crow * N + bn + tx * TN) : nullptr;
        #pragma unroll
        for (int j = 0; j < TN; j++) {
            float v = acc[i][j] + bv[j];
            if (MODE == 1) v = fmaxf(v, 0.f);
            if (MODE == 2) v += Arow2[j];
            Crow[j] = v;
        }
    }
}

// ---------------------------------------------------------------------------
// mpi = concat(memory.reshape(b,8,M), x[:,None,:])  -> [b,9,M]
// ---------------------------------------------------------------------------
__global__ void build_mpi_kernel(const float* __restrict__ mem,
                                 const float* __restrict__ x,
                                 float* __restrict__ mpi)
{
    size_t i = (size_t)blockIdx.x * blockDim.x + threadIdx.x;   // < ROWS_*M_
    int    m   = (int)(i & (M_ - 1));
    size_t row = i >> 10;             // b*9 + s
    size_t b   = row / SP1_;
    int    s   = (int)(row - b * SP1_);
    mpi[i] = (s < S_) ? mem[(b * S_ + s) * M_ + m] : x[b * M_ + m];
}

// ---------------------------------------------------------------------------
// gi[b,0:2] = x[b,:] @ kernel_gi + bias_gi      (one warp per batch row)
// ---------------------------------------------------------------------------
__global__ void gi_kernel(const float* __restrict__ x,
                          const float* __restrict__ kgi,
                          const float* __restrict__ bgi,
                          float* __restrict__ gi)
{
    int b    = blockIdx.x * 8 + (threadIdx.x >> 5);
    int lane = threadIdx.x & 31;
    const float* xr = x + (size_t)b * M_;
    float g0 = 0.f, g1 = 0.f;
    for (int m = lane; m < M_; m += 32) {
        float xv = xr[m];
        g0 = fmaf(xv, kgi[2 * m + 0], g0);
        g1 = fmaf(xv, kgi[2 * m + 1], g1);
    }
    #pragma unroll
    for (int o = 16; o; o >>= 1) {
        g0 += __shfl_xor_sync(0xffffffffu, g0, o);
        g1 += __shfl_xor_sync(0xffffffffu, g1, o);
    }
    if (lane == 0) {
        gi[2 * b + 0] = g0 + bgi[0];
        gi[2 * b + 1] = g1 + bgi[1];
    }
}

// ---------------------------------------------------------------------------
// Attention per (b,h):  w = softmax(q k^T), att = w v ;  m1 = mpi + att
// q = qkv[...,:128]*384^-0.5, k = [128:256), v = [256:384)
// qkv storage: row (b*9+s), col h*384 + c
// ---------------------------------------------------------------------------
__global__ __launch_bounds__(256)
void attn_kernel(const float* __restrict__ qkv,
                 const float* __restrict__ mpi,
                 float* __restrict__ m1)
{
    const int bh = blockIdx.x;
    const int b  = bh >> 3;
    const int h  = bh & 7;

    __shared__ float q [SP1_][128];
    __shared__ float kk[SP1_][128];
    __shared__ float vv[SP1_][128];
    __shared__ float sc[SP1_][SP1_];

    const float scale = rsqrtf((float)QKV_);
    const int tid = threadIdx.x;

    for (int i = tid; i < SP1_ * 128; i += 256) {
        int s = i >> 7, d = i & 127;
        const float* base = qkv + ((size_t)(b * SP1_ + s)) * TOT_ + h * QKV_;
        q [s][d] = base[d] * scale;
        kk[s][d] = base[128 + d];
        vv[s][d] = base[256 + d];
    }
    __syncthreads();

    const int w = tid >> 5, lane = tid & 31;
    for (int idx = w; idx < SP1_ * SP1_; idx += 8) {
        int i = idx / SP1_, j = idx - i * SP1_;
        float s = 0.f;
        for (int d = lane; d < 128; d += 32) s = fmaf(q[i][d], kk[j][d], s);
        #pragma unroll
        for (int o = 16; o; o >>= 1) s += __shfl_xor_sync(0xffffffffu, s, o);
        if (lane == 0) sc[i][j] = s;
    }
    __syncthreads();

    if (tid < SP1_) {
        float mx = -1e30f;
        #pragma unroll
        for (int j = 0; j < SP1_; j++) mx = fmaxf(mx, sc[tid][j]);
        float e[SP1_], sum = 0.f;
        #pragma unroll
        for (int j = 0; j < SP1_; j++) { e[j] = expf(sc[tid][j] - mx); sum += e[j]; }
        float inv = 1.f / sum;
        #pragma unroll
        for (int j = 0; j < SP1_; j++) sc[tid][j] = e[j] * inv;
    }
    __syncthreads();

    for (int i = tid; i < SP1_ * 128; i += 256) {
        int s = i >> 7, d = i & 127;
        float acc = 0.f;
        #pragma unroll
        for (int j = 0; j < SP1_; j++) acc = fmaf(sc[s][j], vv[j][d], acc);
        size_t o = ((size_t)(b * SP1_ + s)) * M_ + h * 128 + d;
        m1[o] = mpi[o] + acc;
    }
}

// ---------------------------------------------------------------------------
// Gate epilogue per (b,s):
//   gm = tanh(mem[b,s,:]) @ kernel_gm + bias_gm ; gates = gm + gi[b]
//   out = sigmoid(gates0) * tanh(m2[b,s,:]) + sigmoid(gates1 + 1) * mem[b,s,:]
// ---------------------------------------------------------------------------
__global__ __launch_bounds__(256)
void gate_kernel(const float* __restrict__ mem,
                 const float* __restrict__ m2,
                 const float* __restrict__ kgm,
                 const float* __restrict__ bgm,
                 const float* __restrict__ gi,
                 float* __restrict__ out)
{
    const int bs = blockIdx.x;      // b*8 + s
    const int b  = bs >> 3;
    const int s  = bs & 7;
    const int tid = threadIdx.x;

    const float* mrow  = mem + (size_t)bs * M_;
    const float* m2row = m2  + ((size_t)(b * SP1_ + s)) * M_;

    float g0 = 0.f, g1 = 0.f;
    for (int m = tid; m < M_; m += 256) {
        float t = tanhf(mrow[m]);
        g0 = fmaf(t, kgm[2 * m + 0], g0);
        g1 = fmaf(t, kgm[2 * m + 1], g1);
    }
    #pragma unroll
    for (int o = 16; o; o >>= 1) {
        g0 += __shfl_xor_sync(0xffffffffu, g0, o);
        g1 += __shfl_xor_sync(0xffffffffu, g1, o);
    }
    __shared__ float s0[8], s1[8];
    __shared__ float igs, fgs;
    int w = tid >> 5, lane = tid & 31;
    if (lane == 0) { s0[w] = g0; s1[w] = g1; }
    __syncthreads();
    if (tid == 0) {
        float G0 = 0.f, G1 = 0.f;
        #pragma unroll
        for (int i = 0; i < 8; i++) { G0 += s0[i]; G1 += s1[i]; }
        G0 += bgm[0] + gi[2 * b + 0];          // + INPUT_BIAS (0)
        G1 += bgm[1] + gi[2 * b + 1] + 1.0f;   // + FORGET_BIAS
        igs = 1.f / (1.f + expf(-G0));
        fgs = 1.f / (1.f + expf(-G1));
    }
    __syncthreads();
    const float ig = igs, fg = fgs;

    float* orow = out + (size_t)b * (S_ * M_) + s * M_;
    for (int m = tid; m < M_; m += 256) {
        orow[m] = fmaf(ig, tanhf(m2row[m]), fg * mrow[m]);
    }
}

// ---------------------------------------------------------------------------
// kernel_launch
// ---------------------------------------------------------------------------
extern "C" void kernel_launch(void* const* d_in, const int* in_sizes, int n_in,
                              void* d_out, int out_size)
{
    const float* inputs   = (const float*)d_in[0];
    const float* memory   = (const float*)d_in[1];
    const float* k_qkv    = (const float*)d_in[2];
    const float* b_qkv    = (const float*)d_in[3];
    const float* k_gi     = (const float*)d_in[4];
    const float* b_gi     = (const float*)d_in[5];
    const float* k_gm     = (const float*)d_in[6];
    const float* b_gm     = (const float*)d_in[7];
    const float* k_in     = (const float*)d_in[8];
    const float* b_in     = (const float*)d_in[9];
    const float* mlp_k0   = (const float*)d_in[10];
    const float* mlp_b0   = (const float*)d_in[11];
    const float* mlp_k1   = (const float*)d_in[12];
    const float* mlp_b1   = (const float*)d_in[13];
    float* out = (float*)d_out;

    float *px, *pmpi, *pqkv, *pm1, *ph, *pm2, *pgi;
    cudaGetSymbolAddress((void**)&px,   g_x);
    cudaGetSymbolAddress((void**)&pmpi, g_mpi);
    cudaGetSymbolAddress((void**)&pqkv, g_qkv);
    cudaGetSymbolAddress((void**)&pm1,  g_m1);
    cudaGetSymbolAddress((void**)&ph,   g_h);
    cudaGetSymbolAddress((void**)&pm2,  g_m2);
    cudaGetSymbolAddress((void**)&pgi,  g_gi);

    // 1. x = inputs @ kernel_in + bias_in          (2048, 1024, 1024)
    sgemm_kernel<0><<<dim3(M_ / BN, B_ / BM), 256>>>(
        inputs, k_in, b_in, nullptr, px, B_, M_, M_);

    // 2. mpi = concat(mem, x)
    build_mpi_kernel<<<(unsigned)(((size_t)ROWS_ * M_) / 256), 256>>>(memory, px, pmpi);

    // 3. gi = x @ kernel_gi + bias_gi
    gi_kernel<<<B_ / 8, 256>>>(px, k_gi, b_gi, pgi);

    // 4. qkv = mpi @ kernel_qkv + bias_qkv         (18432, 3072, 1024)
    sgemm_kernel<0><<<dim3(TOT_ / BN, ROWS_ / BM), 256>>>(
        pmpi, k_qkv, b_qkv, nullptr, pqkv, ROWS_, TOT_, M_);

    // 5. attention + residual: m1 = mpi + att
    attn_kernel<<<B_ * H_, 256>>>(pqkv, pmpi, pm1);

    // 6. h = relu(m1 @ mlp_k0 + mlp_b0)            (18432, 1024, 1024)
    sgemm_kernel<1><<<dim3(M_ / BN, ROWS_ / BM), 256>>>(
        pm1, mlp_k0, mlp_b0, nullptr, ph, ROWS_, M_, M_);

    // 7. m2 = m1 + h @ mlp_k1 + mlp_b1             (18432, 1024, 1024)
    sgemm_kernel<2><<<dim3(M_ / BN, ROWS_ / BM), 256>>>(
        ph, mlp_k1, mlp_b1, pm1, pm2, ROWS_, M_, M_);

    // 8. gates + output
    gate_kernel<<<B_ * S_, 256>>>(memory, pm2, k_gm, b_gm, pgi, out);
}

// round 3
// speedup vs baseline: 2.2949x; 2.2949x over previous
#include <cuda_runtime.h>
#include <cuda_bf16.h>
#include <math.h>
#include <stdint.h>

// ---------------------------------------------------------------------------
// RelationalMemoryCell  (B=2048, S=8, H=8, M=1024, QKV=384, TOT=3072)
// Round 3: split-bf16 GEMM on mma.sync (HMMA) — compute_103-safe.
//   A@B ~= Ahi*Bhi + Ahi*Blo + Alo*Bhi   (fp32 accumulate)
// ---------------------------------------------------------------------------

#define B_     2048
#define S_     8
#define H_     8
#define M_     1024
#define QKV_   384
#define TOT_   3072
#define SP1_   9
#define ROWS_  (B_*SP1_)   // 18432

// Scratch (allocation-free rule: __device__ globals)
__device__ float g_x   [(size_t)B_   * M_  ];
__device__ float g_mpi [(size_t)ROWS_* M_  ];
__device__ float g_qkv [(size_t)ROWS_* TOT_];
__device__ float g_m1  [(size_t)ROWS_* M_  ];
__device__ float g_h   [(size_t)ROWS_* M_  ];
__device__ float g_m2  [(size_t)ROWS_* M_  ];
__device__ float g_gi  [(size_t)B_ * 2];

// ---------------------------------------------------------------------------
// helpers
// ---------------------------------------------------------------------------
__device__ __forceinline__ uint32_t smem_u32(const void* p) {
    uint32_t a;
    asm("{ .reg .u64 t; cvta.to.shared.u64 t, %1; cvt.u32.u64 %0, t; }"
        : "=r"(a) : "l"(p));
    return a;
}
__device__ __forceinline__ void sts64(uint32_t addr, uint32_t lo, uint32_t hi) {
    asm volatile("{ .reg .b64 t; mov.b64 t, {%1,%2}; st.shared.b64 [%0], t; }"
                 :: "r"(addr), "r"(lo), "r"(hi) : "memory");
}
__device__ __forceinline__ void ldsm4(uint32_t* r, uint32_t a) {
    asm volatile("ldmatrix.sync.aligned.m8n8.x4.shared.b16 {%0,%1,%2,%3}, [%4];"
        : "=r"(r[0]), "=r"(r[1]), "=r"(r[2]), "=r"(r[3]) : "r"(a));
}
__device__ __forceinline__ void ldsm4t(uint32_t* r, uint32_t a) {
    asm volatile("ldmatrix.sync.aligned.m8n8.x4.trans.shared.b16 {%0,%1,%2,%3}, [%4];"
        : "=r"(r[0]), "=r"(r[1]), "=r"(r[2]), "=r"(r[3]) : "r"(a));
}
__device__ __forceinline__ void mma16816(float* c, const uint32_t* a, const uint32_t* b) {
    asm volatile(
        "mma.sync.aligned.m16n8k16.row.col.f32.bf16.bf16.f32 "
        "{%0,%1,%2,%3}, {%4,%5,%6,%7}, {%8,%9}, {%0,%1,%2,%3};"
        : "+f"(c[0]), "+f"(c[1]), "+f"(c[2]), "+f"(c[3])
        : "r"(a[0]), "r"(a[1]), "r"(a[2]), "r"(a[3]), "r"(b[0]), "r"(b[1]));
}

// split one float4 into hi-bf16x4 (2 regs) and lo-bf16x4 (2 regs)
__device__ __forceinline__ void split4(float4 v, uint32_t* hi, uint32_t* lo) {
    __nv_bfloat162 hxy = __floats2bfloat162_rn(v.x, v.y);
    __nv_bfloat162 hzw = __floats2bfloat162_rn(v.z, v.w);
    float rx = v.x - __bfloat162float(hxy.x);
    float ry = v.y - __bfloat162float(hxy.y);
    float rz = v.z - __bfloat162float(hzw.x);
    float rw = v.w - __bfloat162float(hzw.y);
    __nv_bfloat162 lxy = __floats2bfloat162_rn(rx, ry);
    __nv_bfloat162 lzw = __floats2bfloat162_rn(rz, rw);
    hi[0] = *(uint32_t*)&hxy;  hi[1] = *(uint32_t*)&hzw;
    lo[0] = *(uint32_t*)&lxy;  lo[1] = *(uint32_t*)&lzw;
}

// ---------------------------------------------------------------------------
// Split-bf16 HMMA GEMM:  C[Mr,N] = epi(A[Mr,K] @ Bg[K,N] + bias)
// MODE 0: +bias   MODE 1: relu(+bias)   MODE 2: Cadd + (+bias)
// Tile 128x128, BK=32, 512 threads (16 warps, 4x4), double-buffered SMEM.
// SMEM per buffer: Ahi 128x80B, Alo 128x80B, Bhi 32x272B, Blo 32x272B
//   (padded strides -> conflict-free ldmatrix)
// ---------------------------------------------------------------------------
#define AST   80u          // A smem row stride (bytes), 32 bf16 data + pad
#define BST   272u         // B smem row stride (bytes), 128 bf16 data + pad
#define OFF_ALO 10240u
#define OFF_BHI 20480u
#define OFF_BLO 29184u
#define BUFSZ   37888u
#define DSMEM  (2 * 37888)

template<int MODE>
__global__ __launch_bounds__(512)
void hgemm_kernel(const float* __restrict__ A, const float* __restrict__ Bg,
                  const float* __restrict__ bias, const float* __restrict__ Cadd,
                  float* __restrict__ C, int N, int K)
{
    extern __shared__ char sm_[];
    const uint32_t sbase = smem_u32(sm_);

    const int tid  = threadIdx.x;
    const int wid  = tid >> 5;
    const int lane = tid & 31;
    const int wm   = (wid & 3) << 5;     // warp m offset (0,32,64,96)
    const int wn   = (wid >> 2) << 5;    // warp n offset (0,32,64,96)
    const int bm   = blockIdx.y << 7;
    const int bn   = blockIdx.x << 7;

    float acc[2][4][4];
    #pragma unroll
    for (int i = 0; i < 2; i++)
        #pragma unroll
        for (int j = 0; j < 4; j++)
            #pragma unroll
            for (int k = 0; k < 4; k++) acc[i][j][k] = 0.f;

    // loader slot indices (2 slots each for A and B)
    const int aRow0 = tid >> 3,  aC0 = tid & 7;          // slots 0..511
    const int aRow1 = (tid + 512) >> 3, aC1 = (tid + 512) & 7;
    const int bRow0 = tid >> 5,  bC0 = tid & 31;
    const int bRow1 = (tid + 512) >> 5, bC1 = (tid + 512) & 31;

    const float* Ab = A + (size_t)bm * K;
    const float* Bb = Bg + bn;

    const int nchunk = K >> 5;
    float4 ar0, ar1, br0, br1;

    // ---- load chunk 0 into regs ----
    {
        ar0 = __ldg((const float4*)(Ab + (size_t)aRow0 * K + (aC0 << 2)));
        ar1 = __ldg((const float4*)(Ab + (size_t)aRow1 * K + (aC1 << 2)));
        br0 = __ldg((const float4*)(Bb + (size_t)bRow0 * N + (bC0 << 2)));
        br1 = __ldg((const float4*)(Bb + (size_t)bRow1 * N + (bC1 << 2)));
    }
    // ---- store chunk 0 to buffer 0 ----
    {
        uint32_t tb = sbase;
        uint32_t h[2], l[2];
        split4(ar0, h, l);
        sts64(tb + (uint32_t)aRow0 * AST + (uint32_t)(aC0 << 3), h[0], h[1]);
        sts64(tb + OFF_ALO + (uint32_t)aRow0 * AST + (uint32_t)(aC0 << 3), l[0], l[1]);
        split4(ar1, h, l);
        sts64(tb + (uint32_t)aRow1 * AST + (uint32_t)(aC1 << 3), h[0], h[1]);
        sts64(tb + OFF_ALO + (uint32_t)aRow1 * AST + (uint32_t)(aC1 << 3), l[0], l[1]);
        split4(br0, h, l);
        sts64(tb + OFF_BHI + (uint32_t)bRow0 * BST + (uint32_t)(bC0 << 3), h[0], h[1]);
        sts64(tb + OFF_BLO + (uint32_t)bRow0 * BST + (uint32_t)(bC0 << 3), l[0], l[1]);
        split4(br1, h, l);
        sts64(tb + OFF_BHI + (uint32_t)bRow1 * BST + (uint32_t)(bC1 << 3), h[0], h[1]);
        sts64(tb + OFF_BLO + (uint32_t)bRow1 * BST + (uint32_t)(bC1 << 3), l[0], l[1]);
    }
    __syncthreads();

    #pragma unroll 1
    for (int c = 0; c < nchunk; c++) {
        const uint32_t tb = sbase + (uint32_t)(c & 1) * BUFSZ;

        // prefetch next chunk into regs
        if (c + 1 < nchunk) {
            const int k0 = (c + 1) << 5;
            ar0 = __ldg((const float4*)(Ab + (size_t)aRow0 * K + k0 + (aC0 << 2)));
            ar1 = __ldg((const float4*)(Ab + (size_t)aRow1 * K + k0 + (aC1 << 2)));
            br0 = __ldg((const float4*)(Bb + (size_t)(k0 + bRow0) * N + (bC0 << 2)));
            br1 = __ldg((const float4*)(Bb + (size_t)(k0 + bRow1) * N + (bC1 << 2)));
        }

        // ---- compute on buffer c ----
        const uint32_t aHi = tb, aLo = tb + OFF_ALO;
        const uint32_t bHi = tb + OFF_BHI, bLo = tb + OFF_BLO;
        #pragma unroll
        for (int s = 0; s < 3; s++) {
            const uint32_t aB = (s == 2) ? aLo : aHi;
            const uint32_t bB = (s == 1) ? bLo : bHi;
            #pragma unroll
            for (int ks = 0; ks < 2; ks++) {
                uint32_t ra[2][4], rb[2][4];
                uint32_t aAd = aB + (uint32_t)(wm + (lane & 15)) * AST
                             + (uint32_t)(ks << 5) + (uint32_t)((lane >> 4) << 4);
                ldsm4(ra[0], aAd);
                ldsm4(ra[1], aAd + 16u * AST);
                uint32_t bAd = bB + (uint32_t)((ks << 4) + (lane & 15)) * BST
                             + (uint32_t)(wn << 1) + (uint32_t)((lane >> 4) << 4);
                ldsm4t(rb[0], bAd);
                ldsm4t(rb[1], bAd + 32u);
                #pragma unroll
                for (int mt = 0; mt < 2; mt++)
                    #pragma unroll
                    for (int nt = 0; nt < 4; nt++)
                        mma16816(acc[mt][nt], ra[mt], &rb[nt >> 1][(nt & 1) << 1]);
            }
        }

        // store next chunk to other buffer
        if (c + 1 < nchunk) {
            const uint32_t nb = sbase + (uint32_t)((c + 1) & 1) * BUFSZ;
            uint32_t h[2], l[2];
            split4(ar0, h, l);
            sts64(nb + (uint32_t)aRow0 * AST + (uint32_t)(aC0 << 3), h[0], h[1]);
            sts64(nb + OFF_ALO + (uint32_t)aRow0 * AST + (uint32_t)(aC0 << 3), l[0], l[1]);
            split4(ar1, h, l);
            sts64(nb + (uint32_t)aRow1 * AST + (uint32_t)(aC1 << 3), h[0], h[1]);
            sts64(nb + OFF_ALO + (uint32_t)aRow1 * AST + (uint32_t)(aC1 << 3), l[0], l[1]);
            split4(br0, h, l);
            sts64(nb + OFF_BHI + (uint32_t)bRow0 * BST + (uint32_t)(bC0 << 3), h[0], h[1]);
            sts64(nb + OFF_BLO + (uint32_t)bRow0 * BST + (uint32_t)(bC0 << 3), l[0], l[1]);
            split4(br1, h, l);
            sts64(nb + OFF_BHI + (uint32_t)bRow1 * BST + (uint32_t)(bC1 << 3), h[0], h[1]);
            sts64(nb + OFF_BLO + (uint32_t)bRow1 * BST + (uint32_t)(bC1 << 3), l[0], l[1]);
        }
        __syncthreads();
    }

    // ---- epilogue ----
    #pragma unroll
    for (int mt = 0; mt < 2; mt++) {
        #pragma unroll
        for (int nt = 0; nt < 4; nt++) {
            const int m = bm + wm + (mt << 4) + (lane >> 2);
            const int n = bn + wn + (nt << 3) + ((lane & 3) << 1);
            const float b0 = __ldg(&bias[n]);
            const float b1 = __ldg(&bias[n + 1]);
            float2 v0, v1;
            v0.x = acc[mt][nt][0] + b0;  v0.y = acc[mt][nt][1] + b1;
            v1.x = acc[mt][nt][2] + b0;  v1.y = acc[mt][nt][3] + b1;
            if (MODE == 1) {
                v0.x = fmaxf(v0.x, 0.f); v0.y = fmaxf(v0.y, 0.f);
                v1.x = fmaxf(v1.x, 0.f); v1.y = fmaxf(v1.y, 0.f);
            }
            if (MODE == 2) {
                float2 a0 = *(const float2*)(Cadd + (size_t)m * N + n);
                float2 a1 = *(const float2*)(Cadd + (size_t)(m + 8) * N + n);
                v0.x += a0.x; v0.y += a0.y;
                v1.x += a1.x; v1.y += a1.y;
            }
            *(float2*)(C + (size_t)m * N + n)       = v0;
            *(float2*)(C + (size_t)(m + 8) * N + n) = v1;
        }
    }
}

// ---------------------------------------------------------------------------
// mpi = concat(memory.reshape(b,8,M), x[:,None,:])  -> [b,9,M]
// ---------------------------------------------------------------------------
__global__ void build_mpi_kernel(const float* __restrict__ mem,
                                 const float* __restrict__ x,
                                 float* __restrict__ mpi)
{
    size_t i = (size_t)blockIdx.x * blockDim.x + threadIdx.x;
    int    m   = (int)(i & (M_ - 1));
    size_t row = i >> 10;
    size_t b   = row / SP1_;
    int    s   = (int)(row - b * SP1_);
    mpi[i] = (s < S_) ? mem[(b * S_ + s) * M_ + m] : x[b * M_ + m];
}

// ---------------------------------------------------------------------------
// gi[b,0:2] = x[b,:] @ kernel_gi + bias_gi
// ---------------------------------------------------------------------------
__global__ void gi_kernel(const float* __restrict__ x,
                          const float* __restrict__ kgi,
                          const float* __restrict__ bgi,
                          float* __restrict__ gi)
{
    int b    = blockIdx.x * 8 + (threadIdx.x >> 5);
    int lane = threadIdx.x & 31;
    const float* xr = x + (size_t)b * M_;
    float g0 = 0.f, g1 = 0.f;
    for (int m = lane; m < M_; m += 32) {
        float xv = xr[m];
        g0 = fmaf(xv, kgi[2 * m + 0], g0);
        g1 = fmaf(xv, kgi[2 * m + 1], g1);
    }
    #pragma unroll
    for (int o = 16; o; o >>= 1) {
        g0 += __shfl_xor_sync(0xffffffffu, g0, o);
        g1 += __shfl_xor_sync(0xffffffffu, g1, o);
    }
    if (lane == 0) {
        gi[2 * b + 0] = g0 + bgi[0];
        gi[2 * b + 1] = g1 + bgi[1];
    }
}

// ---------------------------------------------------------------------------
// Attention per (b,h) + residual:  m1 = mpi + softmax(q k^T) v
// ---------------------------------------------------------------------------
__global__ __launch_bounds__(256)
void attn_kernel(const float* __restrict__ qkv,
                 const float* __restrict__ mpi,
                 float* __restrict__ m1)
{
    const int bh = blockIdx.x;
    const int b  = bh >> 3;
    const int h  = bh & 7;

    __shared__ float q [SP1_][128];
    __shared__ float kk[SP1_][128];
    __shared__ float vv[SP1_][128];
    __shared__ float sc[SP1_][SP1_];

    const float scale = rsqrtf((float)QKV_);
    const int tid = threadIdx.x;

    for (int i = tid; i < SP1_ * 128; i += 256) {
        int s = i >> 7, d = i & 127;
        const float* base = qkv + ((size_t)(b * SP1_ + s)) * TOT_ + h * QKV_;
        q [s][d] = base[d] * scale;
        kk[s][d] = base[128 + d];
        vv[s][d] = base[256 + d];
    }
    __syncthreads();

    const int w = tid >> 5, lane = tid & 31;
    for (int idx = w; idx < SP1_ * SP1_; idx += 8) {
        int i = idx / SP1_, j = idx - i * SP1_;
        float s = 0.f;
        for (int d = lane; d < 128; d += 32) s = fmaf(q[i][d], kk[j][d], s);
        #pragma unroll
        for (int o = 16; o; o >>= 1) s += __shfl_xor_sync(0xffffffffu, s, o);
        if (lane == 0) sc[i][j] = s;
    }
    __syncthreads();

    if (tid < SP1_) {
        float mx = -1e30f;
        #pragma unroll
        for (int j = 0; j < SP1_; j++) mx = fmaxf(mx, sc[tid][j]);
        float e[SP1_], sum = 0.f;
        #pragma unroll
        for (int j = 0; j < SP1_; j++) { e[j] = expf(sc[tid][j] - mx); sum += e[j]; }
        float inv = 1.f / sum;
        #pragma unroll
        for (int j = 0; j < SP1_; j++) sc[tid][j] = e[j] * inv;
    }
    __syncthreads();

    for (int i = tid; i < SP1_ * 128; i += 256) {
        int s = i >> 7, d = i & 127;
        float acc = 0.f;
        #pragma unroll
        for (int j = 0; j < SP1_; j++) acc = fmaf(sc[s][j], vv[j][d], acc);
        size_t o = ((size_t)(b * SP1_ + s)) * M_ + h * 128 + d;
        m1[o] = mpi[o] + acc;
    }
}

// ---------------------------------------------------------------------------
// Gate epilogue per (b,s)
// ---------------------------------------------------------------------------
__global__ __launch_bounds__(256)
void gate_kernel(const float* __restrict__ mem,
                 const float* __restrict__ m2,
                 const float* __restrict__ kgm,
                 const float* __restrict__ bgm,
                 const float* __restrict__ gi,
                 float* __restrict__ out)
{
    const int bs = blockIdx.x;
    const int b  = bs >> 3;
    const int s  = bs & 7;
    const int tid = threadIdx.x;

    const float* mrow  = mem + (size_t)bs * M_;
    const float* m2row = m2  + ((size_t)(b * SP1_ + s)) * M_;

    float g0 = 0.f, g1 = 0.f;
    for (int m = tid; m < M_; m += 256) {
        float t = tanhf(mrow[m]);
        g0 = fmaf(t, kgm[2 * m + 0], g0);
        g1 = fmaf(t, kgm[2 * m + 1], g1);
    }
    #pragma unroll
    for (int o = 16; o; o >>= 1) {
        g0 += __shfl_xor_sync(0xffffffffu, g0, o);
        g1 += __shfl_xor_sync(0xffffffffu, g1, o);
    }
    __shared__ float s0[8], s1[8];
    __shared__ float igs, fgs;
    int w = tid >> 5, lane = tid & 31;
    if (lane == 0) { s0[w] = g0; s1[w] = g1; }
    __syncthreads();
    if (tid == 0) {
        float G0 = 0.f, G1 = 0.f;
        #pragma unroll
        for (int i = 0; i < 8; i++) { G0 += s0[i]; G1 += s1[i]; }
        G0 += bgm[0] + gi[2 * b + 0];
        G1 += bgm[1] + gi[2 * b + 1] + 1.0f;
        igs = 1.f / (1.f + expf(-G0));
        fgs = 1.f / (1.f + expf(-G1));
    }
    __syncthreads();
    const float ig = igs, fg = fgs;

    float* orow = out + (size_t)b * (S_ * M_) + s * M_;
    for (int m = tid; m < M_; m += 256) {
        orow[m] = fmaf(ig, tanhf(m2row[m]), fg * mrow[m]);
    }
}

// ---------------------------------------------------------------------------
// kernel_launch
// ---------------------------------------------------------------------------
extern "C" void kernel_launch(void* const* d_in, const int* in_sizes, int n_in,
                              void* d_out, int out_size)
{
    const float* inputs   = (const float*)d_in[0];
    const float* memory   = (const float*)d_in[1];
    const float* k_qkv    = (const float*)d_in[2];
    const float* b_qkv    = (const float*)d_in[3];
    const float* k_gi     = (const float*)d_in[4];
    const float* b_gi     = (const float*)d_in[5];
    const float* k_gm     = (const float*)d_in[6];
    const float* b_gm     = (const float*)d_in[7];
    const float* k_in     = (const float*)d_in[8];
    const float* b_in     = (const float*)d_in[9];
    const float* mlp_k0   = (const float*)d_in[10];
    const float* mlp_b0   = (const float*)d_in[11];
    const float* mlp_k1   = (const float*)d_in[12];
    const float* mlp_b1   = (const float*)d_in[13];
    float* out = (float*)d_out;

    float *px, *pmpi, *pqkv, *pm1, *ph, *pm2, *pgi;
    cudaGetSymbolAddress((void**)&px,   g_x);
    cudaGetSymbolAddress((void**)&pmpi, g_mpi);
    cudaGetSymbolAddress((void**)&pqkv, g_qkv);
    cudaGetSymbolAddress((void**)&pm1,  g_m1);
    cudaGetSymbolAddress((void**)&ph,   g_h);
    cudaGetSymbolAddress((void**)&pm2,  g_m2);
    cudaGetSymbolAddress((void**)&pgi,  g_gi);

    cudaFuncSetAttribute(hgemm_kernel<0>, cudaFuncAttributeMaxDynamicSharedMemorySize, DSMEM);
    cudaFuncSetAttribute(hgemm_kernel<1>, cudaFuncAttributeMaxDynamicSharedMemorySize, DSMEM);
    cudaFuncSetAttribute(hgemm_kernel<2>, cudaFuncAttributeMaxDynamicSharedMemorySize, DSMEM);

    // 1. x = inputs @ kernel_in + bias_in          (2048 x 1024 x 1024)
    hgemm_kernel<0><<<dim3(M_ / 128, B_ / 128), 512, DSMEM>>>(
        inputs, k_in, b_in, nullptr, px, M_, M_);

    // 2. mpi = concat(mem, x)
    build_mpi_kernel<<<(unsigned)(((size_t)ROWS_ * M_) / 256), 256>>>(memory, px, pmpi);

    // 3. gi = x @ kernel_gi + bias_gi
    gi_kernel<<<B_ / 8, 256>>>(px, k_gi, b_gi, pgi);

    // 4. qkv = mpi @ kernel_qkv + bias_qkv         (18432 x 3072 x 1024)
    hgemm_kernel<0><<<dim3(TOT_ / 128, ROWS_ / 128), 512, DSMEM>>>(
        pmpi, k_qkv, b_qkv, nullptr, pqkv, TOT_, M_);

    // 5. attention + residual
    attn_kernel<<<B_ * H_, 256>>>(pqkv, pmpi, pm1);

    // 6. h = relu(m1 @ mlp_k0 + mlp_b0)            (18432 x 1024 x 1024)
    hgemm_kernel<1><<<dim3(M_ / 128, ROWS_ / 128), 512, DSMEM>>>(
        pm1, mlp_k0, mlp_b0, nullptr, ph, M_, M_);

    // 7. m2 = m1 + h @ mlp_k1 + mlp_b1             (18432 x 1024 x 1024)
    hgemm_kernel<2><<<dim3(M_ / 128, ROWS_ / 128), 512, DSMEM>>>(
        ph, mlp_k1, mlp_b1, pm1, pm2, M_, M_);

    // 8. gates + output
    gate_kernel<<<B_ * S_, 256>>>(memory, pm2, k_gm, b_gm, pgi, out);
}

// round 4
// speedup vs baseline: 2.5186x; 1.0975x over previous
#include <cuda_runtime.h>
#include <cuda_bf16.h>
#include <math.h>
#include <stdint.h>

// ---------------------------------------------------------------------------
// RelationalMemoryCell  (B=2048, S=8, H=8, M=1024, QKV=384, TOT=3072)
// Round 4: split-bf16 HMMA GEMM, pre-split operands in global, cp.async
// 3-stage pipeline, hoisted ldmatrix. A@B ~= AhBh + AhBl + AlBh (fp32 acc).
// ---------------------------------------------------------------------------

#define B_     2048
#define S_     8
#define H_     8
#define M_     1024
#define QKV_   384
#define TOT_   3072
#define SP1_   9
#define ROWS_  (B_*SP1_)   // 18432

typedef __nv_bfloat16  bf16;
typedef __nv_bfloat162 bf162;

// ---- global scratch (allocation-free rule) ----
__device__ __align__(256) float g_x   [(size_t)B_   * M_  ];
__device__ __align__(256) float g_qkv [(size_t)ROWS_* TOT_];
__device__ __align__(256) float g_m2  [(size_t)ROWS_* M_  ];
__device__ __align__(256) float g_gi  [(size_t)B_ * 2];

__device__ __align__(256) bf16 g_in_hi [(size_t)B_ * M_];
__device__ __align__(256) bf16 g_in_lo [(size_t)B_ * M_];
// weights arena: k_in @0 (1M), k_qkv @1M (3M), mlp_k0 @4M (1M), mlp_k1 @5M (1M)
__device__ __align__(256) bf16 g_w_hi [(size_t)6 * M_ * M_];
__device__ __align__(256) bf16 g_w_lo [(size_t)6 * M_ * M_];
__device__ __align__(256) bf16 g_mpi_hi [(size_t)ROWS_ * M_];
__device__ __align__(256) bf16 g_mpi_lo [(size_t)ROWS_ * M_];
__device__ __align__(256) bf16 g_m1_hi  [(size_t)ROWS_ * M_];
__device__ __align__(256) bf16 g_m1_lo  [(size_t)ROWS_ * M_];
__device__ __align__(256) bf16 g_h_hi   [(size_t)ROWS_ * M_];
__device__ __align__(256) bf16 g_h_lo   [(size_t)ROWS_ * M_];

// ---------------------------------------------------------------------------
// helpers
// ---------------------------------------------------------------------------
__device__ __forceinline__ uint32_t smem_u32(const void* p) {
    uint32_t a;
    asm("{ .reg .u64 t; cvta.to.shared.u64 t, %1; cvt.u32.u64 %0, t; }"
        : "=r"(a) : "l"(p));
    return a;
}
__device__ __forceinline__ void cp16(uint32_t dst, const void* src) {
    asm volatile("cp.async.cg.shared.global [%0], [%1], 16;"
                 :: "r"(dst), "l"(src) : "memory");
}
#define CP_COMMIT() asm volatile("cp.async.commit_group;" ::: "memory")
#define CP_WAIT1()  asm volatile("cp.async.wait_group 1;"  ::: "memory")

__device__ __forceinline__ void ldsm4(uint32_t* r, uint32_t a) {
    asm volatile("ldmatrix.sync.aligned.m8n8.x4.shared.b16 {%0,%1,%2,%3}, [%4];"
        : "=r"(r[0]), "=r"(r[1]), "=r"(r[2]), "=r"(r[3]) : "r"(a));
}
__device__ __forceinline__ void ldsm4t(uint32_t* r, uint32_t a) {
    asm volatile("ldmatrix.sync.aligned.m8n8.x4.trans.shared.b16 {%0,%1,%2,%3}, [%4];"
        : "=r"(r[0]), "=r"(r[1]), "=r"(r[2]), "=r"(r[3]) : "r"(a));
}
__device__ __forceinline__ void mma16816(float* c, const uint32_t* a, const uint32_t* b) {
    asm volatile(
        "mma.sync.aligned.m16n8k16.row.col.f32.bf16.bf16.f32 "
        "{%0,%1,%2,%3}, {%4,%5,%6,%7}, {%8,%9}, {%0,%1,%2,%3};"
        : "+f"(c[0]), "+f"(c[1]), "+f"(c[2]), "+f"(c[3])
        : "r"(a[0]), "r"(a[1]), "r"(a[2]), "r"(a[3]), "r"(b[0]), "r"(b[1]));
}
__device__ __forceinline__ void split1(float v, bf16& hi, bf16& lo) {
    hi = __float2bfloat16_rn(v);
    lo = __float2bfloat16_rn(v - __bfloat162float(hi));
}

// ---------------------------------------------------------------------------
// split_kernel: fp32 -> (hi, lo) bf16, vectorized by 4. n % 4 == 0.
// ---------------------------------------------------------------------------
__global__ void split_kernel(const float* __restrict__ src,
                             bf16* __restrict__ hi, bf16* __restrict__ lo,
                             int n4)
{
    int i = blockIdx.x * blockDim.x + threadIdx.x;
    if (i >= n4) return;
    float4 v = __ldg((const float4*)src + i);
    bf16 h0, h1, h2, h3, l0, l1, l2, l3;
    split1(v.x, h0, l0); split1(v.y, h1, l1);
    split1(v.z, h2, l2); split1(v.w, h3, l3);
    bf162* H = (bf162*)hi + 2 * i;
    bf162* L = (bf162*)lo + 2 * i;
    H[0] = bf162(h0, h1); H[1] = bf162(h2, h3);
    L[0] = bf162(l0, l1); L[1] = bf162(l2, l3);
}

// ---------------------------------------------------------------------------
// Split-bf16 HMMA GEMM, pre-split operands, cp.async 3-stage pipeline.
// C[Mr,N] = epi(A @ B + bias)
// MODE 0: fp32 out (+bias)
// MODE 1: relu(+bias) -> split bf16 out (Chi/Clo)
// MODE 2: fp32 out = (Rhi+Rlo) + (+bias)
// Tile 128x128, BK=32, 512 threads (16 warps, 4x4 grid).
// ---------------------------------------------------------------------------
#define AST     80u
#define BST     272u
#define OFF_ALO 10240u
#define OFF_BHI 20480u
#define OFF_BLO 29184u
#define BUFSZ   37888u
#define NSTAGE  3
#define DSMEM   (NSTAGE * 37888)

template<int MODE>
__global__ __launch_bounds__(512)
void hgemm_kernel(const bf16* __restrict__ Ahi, const bf16* __restrict__ Alo,
                  const bf16* __restrict__ Bhi, const bf16* __restrict__ Blo,
                  const float* __restrict__ bias,
                  const bf16* __restrict__ Rhi, const bf16* __restrict__ Rlo,
                  float* __restrict__ Cf,
                  bf16* __restrict__ Chi, bf16* __restrict__ Clo,
                  int N, int K)
{
    extern __shared__ char sm_[];
    const uint32_t sbase = smem_u32(sm_);

    const int tid  = threadIdx.x;
    const int wid  = tid >> 5;
    const int lane = tid & 31;
    const int wm   = (wid & 3) << 5;
    const int wn   = (wid >> 2) << 5;
    const int bm   = blockIdx.y << 7;
    const int bn   = blockIdx.x << 7;

    // loader slots: A 128 rows x 4 segs; B 32 rows x 16 segs
    const int arow = tid >> 2, aseg = tid & 3;
    const int brow = tid >> 4, bseg = tid & 15;

    const bf16* ApH = Ahi + (size_t)(bm + arow) * K + (aseg << 3);
    const bf16* ApL = Alo + (size_t)(bm + arow) * K + (aseg << 3);
    const bf16* BpH = Bhi + (size_t)brow * N + bn + (bseg << 3);
    const bf16* BpL = Blo + (size_t)brow * N + bn + (bseg << 3);
    const uint32_t aDst = (uint32_t)arow * AST + (uint32_t)(aseg << 4);
    const uint32_t bDst = (uint32_t)brow * BST + (uint32_t)(bseg << 4);

    const int nchunk = K >> 5;

    float acc[2][4][4];
    #pragma unroll
    for (int i = 0; i < 2; i++)
        #pragma unroll
        for (int j = 0; j < 4; j++)
            #pragma unroll
            for (int k = 0; k < 4; k++) acc[i][j][k] = 0.f;

    // prologue: stages 0, 1
    #pragma unroll
    for (int s = 0; s < NSTAGE - 1; s++) {
        const uint32_t sb = sbase + (uint32_t)s * BUFSZ;
        cp16(sb + aDst,           ApH + (s << 5));
        cp16(sb + OFF_ALO + aDst, ApL + (s << 5));
        cp16(sb + OFF_BHI + bDst, BpH + (size_t)(s << 5) * N);
        cp16(sb + OFF_BLO + bDst, BpL + (size_t)(s << 5) * N);
        CP_COMMIT();
    }

    // ldmatrix addresses (depend only on lane/warp)
    const uint32_t aOffBase = (uint32_t)(wm + (lane & 15)) * AST
                            + (uint32_t)((lane >> 4) << 4);
    const uint32_t bOffBase = (uint32_t)(lane & 15) * BST
                            + (uint32_t)(wn << 1) + (uint32_t)((lane >> 4) << 4);

    #pragma unroll 1
    for (int c = 0; c < nchunk; c++) {
        CP_WAIT1();
        __syncthreads();

        const uint32_t tb = sbase + (uint32_t)(c % NSTAGE) * BUFSZ;

        #pragma unroll
        for (int ks = 0; ks < 2; ks++) {
            uint32_t raH[2][4], raL[2][4], rbH[2][4], rbL[2][4];
            const uint32_t aAd = tb + aOffBase + (uint32_t)(ks << 5);
            ldsm4(raH[0], aAd);
            ldsm4(raH[1], aAd + 16u * AST);
            ldsm4(raL[0], aAd + OFF_ALO);
            ldsm4(raL[1], aAd + OFF_ALO + 16u * AST);
            const uint32_t bAd = tb + bOffBase + (uint32_t)(ks << 4) * BST;
            ldsm4t(rbH[0], bAd + OFF_BHI);
            ldsm4t(rbH[1], bAd + OFF_BHI + 32u);
            ldsm4t(rbL[0], bAd + OFF_BLO);
            ldsm4t(rbL[1], bAd + OFF_BLO + 32u);
            #pragma unroll
            for (int mt = 0; mt < 2; mt++)
                #pragma unroll
                for (int nt = 0; nt < 4; nt++) {
                    mma16816(acc[mt][nt], raH[mt], &rbH[nt >> 1][(nt & 1) << 1]);
                    mma16816(acc[mt][nt], raH[mt], &rbL[nt >> 1][(nt & 1) << 1]);
                    mma16816(acc[mt][nt], raL[mt], &rbH[nt >> 1][(nt & 1) << 1]);
                }
        }

        // issue stage c+2
        const int cn = c + NSTAGE - 1;
        if (cn < nchunk) {
            const uint32_t nb = sbase + (uint32_t)(cn % NSTAGE) * BUFSZ;
            cp16(nb + aDst,           ApH + (cn << 5));
            cp16(nb + OFF_ALO + aDst, ApL + (cn << 5));
            cp16(nb + OFF_BHI + bDst, BpH + (size_t)(cn << 5) * N);
            cp16(nb + OFF_BLO + bDst, BpL + (size_t)(cn << 5) * N);
        }
        CP_COMMIT();   // unconditional (empty groups keep the count uniform)
    }

    // ---- epilogue ----
    #pragma unroll
    for (int mt = 0; mt < 2; mt++) {
        #pragma unroll
        for (int nt = 0; nt < 4; nt++) {
            const int m = bm + wm + (mt << 4) + (lane >> 2);
            const int n = bn + wn + (nt << 3) + ((lane & 3) << 1);
            const float b0 = __ldg(&bias[n]);
            const float b1 = __ldg(&bias[n + 1]);
            float2 v0, v1;
            v0.x = acc[mt][nt][0] + b0;  v0.y = acc[mt][nt][1] + b1;
            v1.x = acc[mt][nt][2] + b0;  v1.y = acc[mt][nt][3] + b1;
            const size_t i0 = (size_t)m * N + n;
            const size_t i1 = (size_t)(m + 8) * N + n;
            if (MODE == 0) {
                *(float2*)(Cf + i0) = v0;
                *(float2*)(Cf + i1) = v1;
            }
            if (MODE == 1) {
                v0.x = fmaxf(v0.x, 0.f); v0.y = fmaxf(v0.y, 0.f);
                v1.x = fmaxf(v1.x, 0.f); v1.y = fmaxf(v1.y, 0.f);
                bf16 h0, h1, l0, l1;
                split1(v0.x, h0, l0); split1(v0.y, h1, l1);
                *(bf162*)(Chi + i0) = bf162(h0, h1);
                *(bf162*)(Clo + i0) = bf162(l0, l1);
                split1(v1.x, h0, l0); split1(v1.y, h1, l1);
                *(bf162*)(Chi + i1) = bf162(h0, h1);
                *(bf162*)(Clo + i1) = bf162(l0, l1);
            }
            if (MODE == 2) {
                bf162 rh0 = *(const bf162*)(Rhi + i0);
                bf162 rl0 = *(const bf162*)(Rlo + i0);
                bf162 rh1 = *(const bf162*)(Rhi + i1);
                bf162 rl1 = *(const bf162*)(Rlo + i1);
                v0.x += __bfloat162float(rh0.x) + __bfloat162float(rl0.x);
                v0.y += __bfloat162float(rh0.y) + __bfloat162float(rl0.y);
                v1.x += __bfloat162float(rh1.x) + __bfloat162float(rl1.x);
                v1.y += __bfloat162float(rh1.y) + __bfloat162float(rl1.y);
                *(float2*)(Cf + i0) = v0;
                *(float2*)(Cf + i1) = v1;
            }
        }
    }
}

// ---------------------------------------------------------------------------
// mpi(hi/lo) = split(concat(memory, x))   2 elems per thread
// ---------------------------------------------------------------------------
__global__ void build_mpi_kernel(const float* __restrict__ mem,
                                 const float* __restrict__ x,
                                 bf16* __restrict__ hi, bf16* __restrict__ lo)
{
    size_t i = (size_t)blockIdx.x * blockDim.x + threadIdx.x;  // pair index
    int    mp  = (int)(i & 511);           // pair within row
    size_t row = i >> 9;                   // b*9 + s
    size_t b   = row / SP1_;
    int    s   = (int)(row - b * SP1_);
    const float* src = (s < S_) ? (mem + ((b * S_ + s) << 10)) : (x + (b << 10));
    float2 v = *(const float2*)(src + (mp << 1));
    bf16 h0, h1, l0, l1;
    split1(v.x, h0, l0); split1(v.y, h1, l1);
    ((bf162*)hi)[i] = bf162(h0, h1);
    ((bf162*)lo)[i] = bf162(l0, l1);
}

// ---------------------------------------------------------------------------
// gi[b,0:2] = x[b,:] @ kernel_gi + bias_gi
// ---------------------------------------------------------------------------
__global__ void gi_kernel(const float* __restrict__ x,
                          const float* __restrict__ kgi,
                          const float* __restrict__ bgi,
                          float* __restrict__ gi)
{
    int b    = blockIdx.x * 8 + (threadIdx.x >> 5);
    int lane = threadIdx.x & 31;
    const float* xr = x + (size_t)b * M_;
    float g0 = 0.f, g1 = 0.f;
    for (int m = lane; m < M_; m += 32) {
        float xv = xr[m];
        g0 = fmaf(xv, kgi[2 * m + 0], g0);
        g1 = fmaf(xv, kgi[2 * m + 1], g1);
    }
    #pragma unroll
    for (int o = 16; o; o >>= 1) {
        g0 += __shfl_xor_sync(0xffffffffu, g0, o);
        g1 += __shfl_xor_sync(0xffffffffu, g1, o);
    }
    if (lane == 0) {
        gi[2 * b + 0] = g0 + bgi[0];
        gi[2 * b + 1] = g1 + bgi[1];
    }
}

// ---------------------------------------------------------------------------
// Attention per (b,h):  m1 = (mpi_hi+mpi_lo) + softmax(q k^T) v -> split out
// ---------------------------------------------------------------------------
__global__ __launch_bounds__(256)
void attn_kernel(const float* __restrict__ qkv,
                 const bf16* __restrict__ mpihi, const bf16* __restrict__ mpilo,
                 bf16* __restrict__ m1hi, bf16* __restrict__ m1lo)
{
    const int bh = blockIdx.x;
    const int b  = bh >> 3;
    const int h  = bh & 7;

    __shared__ float q [SP1_][128];
    __shared__ float kk[SP1_][128];
    __shared__ float vv[SP1_][128];
    __shared__ float sc[SP1_][SP1_];

    const float scale = rsqrtf((float)QKV_);
    const int tid = threadIdx.x;

    for (int i = tid; i < SP1_ * 128; i += 256) {
        int s = i >> 7, d = i & 127;
        const float* base = qkv + ((size_t)(b * SP1_ + s)) * TOT_ + h * QKV_;
        q [s][d] = base[d] * scale;
        kk[s][d] = base[128 + d];
        vv[s][d] = base[256 + d];
    }
    __syncthreads();

    const int w = tid >> 5, lane = tid & 31;
    for (int idx = w; idx < SP1_ * SP1_; idx += 8) {
        int i = idx / SP1_, j = idx - i * SP1_;
        float s = 0.f;
        for (int d = lane; d < 128; d += 32) s = fmaf(q[i][d], kk[j][d], s);
        #pragma unroll
        for (int o = 16; o; o >>= 1) s += __shfl_xor_sync(0xffffffffu, s, o);
        if (lane == 0) sc[i][j] = s;
    }
    __syncthreads();

    if (tid < SP1_) {
        float mx = -1e30f;
        #pragma unroll
        for (int j = 0; j < SP1_; j++) mx = fmaxf(mx, sc[tid][j]);
        float e[SP1_], sum = 0.f;
        #pragma unroll
        for (int j = 0; j < SP1_; j++) { e[j] = expf(sc[tid][j] - mx); sum += e[j]; }
        float inv = 1.f / sum;
        #pragma unroll
        for (int j = 0; j < SP1_; j++) sc[tid][j] = e[j] * inv;
    }
    __syncthreads();

    // 2 elems per thread: 576 pairs
    for (int i = tid; i < SP1_ * 64; i += 256) {
        int s  = i >> 6;
        int d  = (i & 63) << 1;
        float a0 = 0.f, a1 = 0.f;
        #pragma unroll
        for (int j = 0; j < SP1_; j++) {
            a0 = fmaf(sc[s][j], vv[j][d],     a0);
            a1 = fmaf(sc[s][j], vv[j][d + 1], a1);
        }
        size_t o = ((size_t)(b * SP1_ + s)) * M_ + h * 128 + d;
        bf162 mh = *(const bf162*)(mpihi + o);
        bf162 ml = *(const bf162*)(mpilo + o);
        float v0 = __bfloat162float(mh.x) + __bfloat162float(ml.x) + a0;
        float v1 = __bfloat162float(mh.y) + __bfloat162float(ml.y) + a1;
        bf16 h0, h1, l0, l1;
        split1(v0, h0, l0); split1(v1, h1, l1);
        *(bf162*)(m1hi + o) = bf162(h0, h1);
        *(bf162*)(m1lo + o) = bf162(l0, l1);
    }
}

// ---------------------------------------------------------------------------
// Gate epilogue per (b,s)
// ---------------------------------------------------------------------------
__global__ __launch_bounds__(256)
void gate_kernel(const float* __restrict__ mem,
                 const float* __restrict__ m2,
                 const float* __restrict__ kgm,
                 const float* __restrict__ bgm,
                 const float* __restrict__ gi,
                 float* __restrict__ out)
{
    const int bs = blockIdx.x;
    const int b  = bs >> 3;
    const int s  = bs & 7;
    const int tid = threadIdx.x;

    const float* mrow  = mem + (size_t)bs * M_;
    const float* m2row = m2  + ((size_t)(b * SP1_ + s)) * M_;

    float g0 = 0.f, g1 = 0.f;
    for (int m = tid; m < M_; m += 256) {
        float t = tanhf(mrow[m]);
        g0 = fmaf(t, kgm[2 * m + 0], g0);
        g1 = fmaf(t, kgm[2 * m + 1], g1);
    }
    #pragma unroll
    for (int o = 16; o; o >>= 1) {
        g0 += __shfl_xor_sync(0xffffffffu, g0, o);
        g1 += __shfl_xor_sync(0xffffffffu, g1, o);
    }
    __shared__ float s0[8], s1[8];
    __shared__ float igs, fgs;
    int w = tid >> 5, lane = tid & 31;
    if (lane == 0) { s0[w] = g0; s1[w] = g1; }
    __syncthreads();
    if (tid == 0) {
        float G0 = 0.f, G1 = 0.f;
        #pragma unroll
        for (int i = 0; i < 8; i++) { G0 += s0[i]; G1 += s1[i]; }
        G0 += bgm[0] + gi[2 * b + 0];
        G1 += bgm[1] + gi[2 * b + 1] + 1.0f;
        igs = 1.f / (1.f + expf(-G0));
        fgs = 1.f / (1.f + expf(-G1));
    }
    __syncthreads();
    const float ig = igs, fg = fgs;

    float* orow = out + (size_t)b * (S_ * M_) + s * M_;
    for (int m = tid; m < M_; m += 256) {
        orow[m] = fmaf(ig, tanhf(m2row[m]), fg * mrow[m]);
    }
}

// ---------------------------------------------------------------------------
// kernel_launch
// ---------------------------------------------------------------------------
extern "C" void kernel_launch(void* const* d_in, const int* in_sizes, int n_in,
                              void* d_out, int out_size)
{
    const float* inputs   = (const float*)d_in[0];
    const float* memory   = (const float*)d_in[1];
    const float* k_qkv    = (const float*)d_in[2];
    const float* b_qkv    = (const float*)d_in[3];
    const float* k_gi     = (const float*)d_in[4];
    const float* b_gi     = (const float*)d_in[5];
    const float* k_gm     = (const float*)d_in[6];
    const float* b_gm     = (const float*)d_in[7];
    const float* k_in     = (const float*)d_in[8];
    const float* b_in     = (const float*)d_in[9];
    const float* mlp_k0   = (const float*)d_in[10];
    const float* mlp_b0   = (const float*)d_in[11];
    const float* mlp_k1   = (const float*)d_in[12];
    const float* mlp_b1   = (const float*)d_in[13];
    float* out = (float*)d_out;

    float *px, *pqkv, *pm2, *pgi;
    bf16 *pinh, *pinl, *pwh, *pwl, *pmpih, *pmpil, *pm1h, *pm1l, *phh, *phl;
    cudaGetSymbolAddress((void**)&px,    g_x);
    cudaGetSymbolAddress((void**)&pqkv,  g_qkv);
    cudaGetSymbolAddress((void**)&pm2,   g_m2);
    cudaGetSymbolAddress((void**)&pgi,   g_gi);
    cudaGetSymbolAddress((void**)&pinh,  g_in_hi);
    cudaGetSymbolAddress((void**)&pinl,  g_in_lo);
    cudaGetSymbolAddress((void**)&pwh,   g_w_hi);
    cudaGetSymbolAddress((void**)&pwl,   g_w_lo);
    cudaGetSymbolAddress((void**)&pmpih, g_mpi_hi);
    cudaGetSymbolAddress((void**)&pmpil, g_mpi_lo);
    cudaGetSymbolAddress((void**)&pm1h,  g_m1_hi);
    cudaGetSymbolAddress((void**)&pm1l,  g_m1_lo);
    cudaGetSymbolAddress((void**)&phh,   g_h_hi);
    cudaGetSymbolAddress((void**)&phl,   g_h_lo);

    const size_t MM = (size_t)M_ * M_;      // 1M
    bf16 *kinH = pwh,          *kinL = pwl;
    bf16 *kqkH = pwh + MM,     *kqkL = pwl + MM;
    bf16 *k0H  = pwh + 4 * MM, *k0L  = pwl + 4 * MM;
    bf16 *k1H  = pwh + 5 * MM, *k1L  = pwl + 5 * MM;

    cudaFuncSetAttribute(hgemm_kernel<0>, cudaFuncAttributeMaxDynamicSharedMemorySize, DSMEM);
    cudaFuncSetAttribute(hgemm_kernel<1>, cudaFuncAttributeMaxDynamicSharedMemorySize, DSMEM);
    cudaFuncSetAttribute(hgemm_kernel<2>, cudaFuncAttributeMaxDynamicSharedMemorySize, DSMEM);

    // 0. split weights + inputs
    split_kernel<<<(B_ * M_ / 4 + 255) / 256, 256>>>(inputs, pinh, pinl, B_ * M_ / 4);
    split_kernel<<<(int)((MM / 4 + 255) / 256), 256>>>(k_in,   kinH, kinL, (int)(MM / 4));
    split_kernel<<<(int)((3 * MM / 4 + 255) / 256), 256>>>(k_qkv, kqkH, kqkL, (int)(3 * MM / 4));
    split_kernel<<<(int)((MM / 4 + 255) / 256), 256>>>(mlp_k0, k0H, k0L, (int)(MM / 4));
    split_kernel<<<(int)((MM / 4 + 255) / 256), 256>>>(mlp_k1, k1H, k1L, (int)(MM / 4));

    // 1. x = inputs @ kernel_in + bias_in
    hgemm_kernel<0><<<dim3(M_ / 128, B_ / 128), 512, DSMEM>>>(
        pinh, pinl, kinH, kinL, b_in, nullptr, nullptr, px, nullptr, nullptr, M_, M_);

    // 2. mpi (split)
    build_mpi_kernel<<<(unsigned)(((size_t)ROWS_ * M_ / 2) / 256), 256>>>(
        memory, px, pmpih, pmpil);

    // 3. gi
    gi_kernel<<<B_ / 8, 256>>>(px, k_gi, b_gi, pgi);

    // 4. qkv = mpi @ kernel_qkv + bias_qkv
    hgemm_kernel<0><<<dim3(TOT_ / 128, ROWS_ / 128), 512, DSMEM>>>(
        pmpih, pmpil, kqkH, kqkL, b_qkv, nullptr, nullptr, pqkv, nullptr, nullptr, TOT_, M_);

    // 5. attention + residual -> m1 (split)
    attn_kernel<<<B_ * H_, 256>>>(pqkv, pmpih, pmpil, pm1h, pm1l);

    // 6. h = relu(m1 @ mlp_k0 + mlp_b0) -> split
    hgemm_kernel<1><<<dim3(M_ / 128, ROWS_ / 128), 512, DSMEM>>>(
        pm1h, pm1l, k0H, k0L, mlp_b0, nullptr, nullptr, nullptr, phh, phl, M_, M_);

    // 7. m2 = m1 + h @ mlp_k1 + mlp_b1
    hgemm_kernel<2><<<dim3(M_ / 128, ROWS_ / 128), 512, DSMEM>>>(
        phh, phl, k1H, k1L, mlp_b1, pm1h, pm1l, pm2, nullptr, nullptr, M_, M_);

    // 8. gates + output
    gate_kernel<<<B_ * S_, 256>>>(memory, pm2, k_gm, b_gm, pgi, out);
}